// round 9
// baseline (speedup 1.0000x reference)
#include <cuda_runtime.h>

#define NN 576
#define MROWS 144
#define ROW_DEG 15
#define EDGES (MROWS * ROW_DEG)
#define BATCH 256
#define ITERS 3
#define SLOTS 16               // max column degree guard (actual max ~12)
#define RW 18                  // 576-bit row mask words
#define CW 5                   // 144-bit col mask words

// Persistent structure (rebuilt deterministically every launch; no allocs).
__device__ short g_cols[EDGES];   // edge (m*15+k) -> column n
__device__ short g_dst[EDGES];    // edge -> n*SLOTS + slot (slot = rank of m in col n)

// ---------------------------------------------------------------------------
// Structure kernel: one CTA, bitmask-based, ~1 memory latency for all of H.
// ---------------------------------------------------------------------------
__global__ __launch_bounds__(1024) void build_struct(const float* __restrict__ H) {
    __shared__ unsigned rowmask[MROWS * RW];   // 10.4 KB
    __shared__ unsigned colmask[NN * CW];      // 11.5 KB

    const int t = threadIdx.x;

    for (int i = t; i < MROWS * RW; i += 1024) rowmask[i] = 0u;
    __syncthreads();

    // A1: H -> row bitmasks. float4 per thread-iter, all loads independent (MLP).
    const float4* H4 = (const float4*)H;
    for (int idx = t; idx < MROWS * (NN / 4); idx += 1024) {
        int m = idx / (NN / 4), c = idx - m * (NN / 4);
        float4 v = H4[idx];
        unsigned nib = (v.x != 0.f) | ((v.y != 0.f) << 1) |
                       ((v.z != 0.f) << 2) | ((v.w != 0.f) << 3);
        if (nib) atomicOr(&rowmask[m * RW + (c >> 3)], nib << ((c & 7) * 4));
    }
    __syncthreads();

    // A2: transpose to column masks (warp-broadcast LDS, conflict-free).
    if (t < NN) {
        const int n = t;
        const int w = n >> 5;
        const unsigned bit = 1u << (n & 31);
        unsigned cm[CW] = {0, 0, 0, 0, 0};
#pragma unroll 8
        for (int m = 0; m < MROWS; m++)
            if (rowmask[m * RW + w] & bit) cm[m >> 5] |= 1u << (m & 31);
#pragma unroll
        for (int ww = 0; ww < CW; ww++) colmask[n * CW + ww] = cm[ww];
    }
    __syncthreads();

    // A3: per-row edge list + destination slots (slot = #rows<m in column n).
    if (t < MROWS) {
        const int m = t;
        const int mw = m >> 5;
        const unsigned mlow = (1u << (m & 31)) - 1u;
        int k = 0;
        for (int j = 0; j < RW; j++) {
            unsigned b = rowmask[m * RW + j];
            while (b) {
                int n = j * 32 + __ffs(b) - 1;
                b &= b - 1;
                int slot = __popc(colmask[n * CW + mw] & mlow);
                for (int ww = 0; ww < mw; ww++) slot += __popc(colmask[n * CW + ww]);
                g_cols[m * ROW_DEG + k] = (short)n;
                g_dst[m * ROW_DEG + k] = (short)(n * SLOTS + slot);
                k++;
            }
        }
    }
}

// ---------------------------------------------------------------------------
// Decoder: ONE batch element per CTA, 144 threads (one per check row).
// Slotted scatter layout: column sum = 4 contiguous LDS.128 + fixed add tree.
// All shared memory STATIC (39 KB < 48 KB) — no attribute calls, no dyn smem.
// ---------------------------------------------------------------------------
#define TPB MROWS
#define QCOL (NN / TPB)        // 4 columns per thread

__global__ void __launch_bounds__(TPB) decode(
    const float* __restrict__ r,
    const float* __restrict__ alpha,
    const float* __restrict__ beta,
    float* __restrict__ out)
{
    __shared__ float sE2[NN * SLOTS];   // 36 KB slotted edge messages
    __shared__ float sL[NN];            // 2.3 KB posterior

    const int t = threadIdx.x;
    const int b = blockIdx.x;

    // Zero sE2 once (unused slots stay 0 forever). 16 STS.128 per thread.
    {
        float4* z = (float4*)sE2;
#pragma unroll
        for (int q = 0; q < (NN * SLOTS / 4) / TPB; q++)
            z[t + q * TPB] = make_float4(0.f, 0.f, 0.f, 0.f);
    }

    // Column ownership: thread t owns n = t + q*TPB, q = 0..3.
    float rcol[QCOL];
#pragma unroll
    for (int q = 0; q < QCOL; q++) {
        int n = t + q * TPB;
        float v = r[b * NN + n];
        rcol[q] = v;
        sL[n] = v;
    }

    // Row ownership + structure in registers (coalesced-ish LDG from L2).
    const int m = t;
    int cols_[ROW_DEG], dst_[ROW_DEG];
#pragma unroll
    for (int k = 0; k < ROW_DEG; k++) {
        cols_[k] = g_cols[m * ROW_DEG + k];
        dst_[k]  = g_dst[m * ROW_DEG + k];
    }
    float E[ROW_DEG];
#pragma unroll
    for (int k = 0; k < ROW_DEG; k++) E[k] = 0.0f;

    const float a0 = alpha[0], a1 = alpha[1], a2 = alpha[2];
    const float o0 = beta[0],  o1 = beta[1],  o2 = beta[2];

    __syncthreads();

#pragma unroll
    for (int it = 0; it < ITERS; it++) {
        const float a   = (it == 0) ? a0 : (it == 1) ? a1 : a2;
        const float ofs = (it == 0) ? o0 : (it == 1) ? o1 : o2;

        // --- check-node (row) update: offset min-sum ---
        float min1 = 3.4e38f, min2 = 3.4e38f;
        int idx = 0;
        unsigned smaskr = 0;
#pragma unroll
        for (int k = 0; k < ROW_DEG; k++) {
            float mv = sL[cols_[k]] - E[k];       // extrinsic input M
            float av = fabsf(mv);
            smaskr |= (__float_as_uint(mv) >> 31) << k;
            if (av < min1) { min2 = min1; min1 = av; idx = k; }
            else if (av < min2) { min2 = av; }
        }
        const float v1 = a * fmaxf(0.0f, min1 - ofs);
        const float v2 = a * fmaxf(0.0f, min2 - ofs);
        const unsigned par = __popc(smaskr) & 1u;
#pragma unroll
        for (int k = 0; k < ROW_DEG; k++) {
            float mag = (k == idx) ? v2 : v1;
            unsigned neg = par ^ ((smaskr >> k) & 1u);
            float e = neg ? -mag : mag;
            E[k] = e;
            sE2[dst_[k]] = e;                     // scatter into column slot
        }
        __syncthreads();

        // --- variable-node (column) update: contiguous vector gather ---
#pragma unroll
        for (int q = 0; q < QCOL; q++) {
            int n = t + q * TPB;
            const float4* p = (const float4*)(sE2 + n * SLOTS);
            float4 x = p[0], y = p[1], z = p[2], w = p[3];
            float s = (((x.x + x.y) + (x.z + x.w)) + ((y.x + y.y) + (y.z + y.w)))
                    + (((z.x + z.y) + (z.z + z.w)) + ((w.x + w.y) + (w.z + w.w)));
            s += rcol[q];
            if (it == ITERS - 1)
                out[b * NN + n] = s;              // final L is the output
            else
                sL[n] = s;
        }
        if (it != ITERS - 1) __syncthreads();
    }
}

extern "C" void kernel_launch(void* const* d_in, const int* in_sizes, int n_in,
                              void* d_out, int out_size) {
    const float* r     = (const float*)d_in[0];   // [256, 576]
    const float* H     = (const float*)d_in[1];   // [144, 576]
    const float* alpha = (const float*)d_in[2];   // [3]
    const float* beta  = (const float*)d_in[3];   // [3]
    float* out = (float*)d_out;                   // [256, 576]

    build_struct<<<1, 1024>>>(H);
    decode<<<BATCH, TPB>>>(r, alpha, beta, out);
}

// round 14
// speedup vs baseline: 1.8668x; 1.8668x over previous
#include <cuda_runtime.h>

#define NN 576
#define MROWS 144
#define ROW_DEG 15
#define EDGES (MROWS * ROW_DEG)
#define BATCH 256
#define ITERS 3
#define STRIDE 20              // padded slot stride (floats): conflict-free LDS.128
#define CW 5                   // 144-bit column mask words

// Persistent structure. Zero-initialized at load; rebuilt idempotently every
// launch (same values / same OR bits each call -> deterministic, no guards).
__device__ unsigned g_colmask[NN * CW];   // column occupancy bitmasks (OR-idempotent)
__device__ short    g_cols[EDGES];        // edge (m*15+k) -> column n
__device__ uint4    g_pack4[MROWS * 4];   // [m]: 16 packed words n | (dst<<16)
                                          // (uint4 => guaranteed 16B alignment for LDG.128)

// ---------------------------------------------------------------------------
// build_a: 144 warps (18 CTAs x 8 warps), one warp per check row.
// Prefetch whole row (18 independent LDGs -> one latency), ballot-scan,
// atomicOr column bits (order-independent => deterministic).
// ---------------------------------------------------------------------------
__global__ __launch_bounds__(256) void build_a(const float* __restrict__ H) {
    const int m = blockIdx.x * 8 + (threadIdx.x >> 5);   // 0..143
    const int lane = threadIdx.x & 31;
    const float* row = H + m * NN;
    float v[18];
#pragma unroll
    for (int j = 0; j < 18; j++) v[j] = row[j * 32 + lane];
    int base = 0;
#pragma unroll
    for (int j = 0; j < 18; j++) {
        unsigned act = __ballot_sync(0xffffffffu, v[j] != 0.0f);
        if (v[j] != 0.0f) {
            int k = base + __popc(act & ((1u << lane) - 1u));
            int n = j * 32 + lane;
            g_cols[m * ROW_DEG + k] = (short)n;
            atomicOr(&g_colmask[n * CW + (m >> 5)], 1u << (m & 31));
        }
        base += __popc(act);
    }
}

// ---------------------------------------------------------------------------
// build_b: one thread per edge. slot = rank of row m within column n
// (popc over column mask below m) -> packed destination table (scalar stores).
// ---------------------------------------------------------------------------
__global__ __launch_bounds__(256) void build_b() {
    const int e = blockIdx.x * 256 + threadIdx.x;
    if (e >= EDGES) return;
    const int m = e / ROW_DEG, k = e - m * ROW_DEG;
    const int n = g_cols[e];
    const int mw = m >> 5;
    const unsigned mlow = (1u << (m & 31)) - 1u;
    int slot = 0;
#pragma unroll
    for (int ww = 0; ww < CW; ww++) {
        unsigned cm = g_colmask[n * CW + ww];
        if (ww < mw) slot += __popc(cm);
        else if (ww == mw) slot += __popc(cm & mlow);
    }
    unsigned dst = (unsigned)(n * STRIDE + slot);
    unsigned* gp = (unsigned*)g_pack4;             // scalar 4B stores: always legal
    gp[m * 16 + k] = (unsigned)n | (dst << 16);
    if (k == 0) gp[m * 16 + 15] = 0;               // pad word
}

// ---------------------------------------------------------------------------
// Decoder: one batch element per CTA, 288 threads (9 full warps).
// Rows on t<144; columns 2 per thread on all 288. Slotted scatter layout with
// stride-20 padding: column sum = 4 conflict-free LDS.128 + fixed add tree.
// Static smem 48384 B (< 48 KB static limit) — no attribute calls.
// ---------------------------------------------------------------------------
#define TPB 288

__global__ void __launch_bounds__(TPB) decode(
    const float* __restrict__ r,
    const float* __restrict__ alpha,
    const float* __restrict__ beta,
    float* __restrict__ out)
{
    __shared__ __align__(16) float sE2[NN * STRIDE];   // 46.1 KB slotted messages
    __shared__ __align__(16) float sL[NN];             // posterior

    const int t = threadIdx.x;
    const int b = blockIdx.x;

    // Zero sE2 once (unused slots stay 0 forever). 10 STS.128 per thread.
    {
        float4* z = (float4*)sE2;
#pragma unroll
        for (int q = 0; q < (NN * STRIDE / 4) / TPB; q++)
            z[t + q * TPB] = make_float4(0.f, 0.f, 0.f, 0.f);
    }

    // Column ownership: thread t owns n = t and n = t + 288.
    float rcol[2];
#pragma unroll
    for (int q = 0; q < 2; q++) {
        int n = t + q * TPB;
        float v = r[b * NN + n];
        rcol[q] = v;
        sL[n] = v;
    }

    // Row structure (threads 0..143): 4x LDG.128 of the packed table.
    int cols_[ROW_DEG], dst_[ROW_DEG];
    float E[ROW_DEG];
#pragma unroll
    for (int k = 0; k < ROW_DEG; k++) { cols_[k] = 0; dst_[k] = 0; E[k] = 0.0f; }
    if (t < MROWS) {
        uint4 pk4[4];
#pragma unroll
        for (int q = 0; q < 4; q++) pk4[q] = g_pack4[t * 4 + q];
        const unsigned* pk = (const unsigned*)pk4;
#pragma unroll
        for (int k = 0; k < ROW_DEG; k++) {
            cols_[k] = pk[k] & 0xFFFFu;
            dst_[k]  = pk[k] >> 16;
        }
    }

    const float a0 = alpha[0], a1 = alpha[1], a2 = alpha[2];
    const float o0 = beta[0],  o1 = beta[1],  o2 = beta[2];

    __syncthreads();

#pragma unroll
    for (int it = 0; it < ITERS; it++) {
        const float a   = (it == 0) ? a0 : (it == 1) ? a1 : a2;
        const float ofs = (it == 0) ? o0 : (it == 1) ? o1 : o2;

        // --- check-node (row) update: offset min-sum (threads 0..143) ---
        if (t < MROWS) {
            float min1 = 3.4e38f, min2 = 3.4e38f;
            int idx = 0;
            unsigned smaskr = 0;
#pragma unroll
            for (int k = 0; k < ROW_DEG; k++) {
                float mv = sL[cols_[k]] - E[k];     // extrinsic input M
                float av = fabsf(mv);
                smaskr |= (__float_as_uint(mv) >> 31) << k;
                if (av < min1) { min2 = min1; min1 = av; idx = k; }
                else if (av < min2) { min2 = av; }
            }
            const float v1 = a * fmaxf(0.0f, min1 - ofs);
            const float v2 = a * fmaxf(0.0f, min2 - ofs);
            const unsigned par = __popc(smaskr) & 1u;
#pragma unroll
            for (int k = 0; k < ROW_DEG; k++) {
                float mag = (k == idx) ? v2 : v1;
                unsigned neg = par ^ ((smaskr >> k) & 1u);
                float e = neg ? -mag : mag;
                E[k] = e;
                sE2[dst_[k]] = e;                   // scatter into column slot
            }
        }
        __syncthreads();

        // --- variable-node (column) update: conflict-free vector gather ---
#pragma unroll
        for (int q = 0; q < 2; q++) {
            int n = t + q * TPB;
            const float4* p = (const float4*)(sE2 + n * STRIDE);
            float4 x = p[0], y = p[1], z = p[2], w = p[3];
            float s = (((x.x + x.y) + (x.z + x.w)) + ((y.x + y.y) + (y.z + y.w)))
                    + (((z.x + z.y) + (z.z + z.w)) + ((w.x + w.y) + (w.z + w.w)));
            s += rcol[q];
            if (it == ITERS - 1)
                out[b * NN + n] = s;                // final L is the output
            else
                sL[n] = s;
        }
        if (it != ITERS - 1) __syncthreads();
    }
}

extern "C" void kernel_launch(void* const* d_in, const int* in_sizes, int n_in,
                              void* d_out, int out_size) {
    const float* r     = (const float*)d_in[0];   // [256, 576]
    const float* H     = (const float*)d_in[1];   // [144, 576]
    const float* alpha = (const float*)d_in[2];   // [3]
    const float* beta  = (const float*)d_in[3];   // [3]
    float* out = (float*)d_out;                   // [256, 576]

    build_a<<<18, 256>>>(H);
    build_b<<<(EDGES + 255) / 256, 256>>>();
    decode<<<BATCH, TPB>>>(r, alpha, beta, out);
}